// round 10
// baseline (speedup 1.0000x reference)
#include <cuda_runtime.h>
#include <cstdint>

#define BB   64
#define SS   1024
#define II   256
#define HH   256
#define G3   768

typedef unsigned long long u64;

// Scratch for input-side gate projections, interleaved:
// g_xg[row][unit][gate] with 4-float padding: float index = row*1024 + j*4 + gate
__device__ float g_xg[(size_t)BB * SS * 1024];

__device__ __forceinline__ u64 ffma2(u64 a, u64 b, u64 c) {
    u64 d; asm("fma.rn.f32x2 %0, %1, %2, %3;" : "=l"(d) : "l"(a), "l"(b), "l"(c)); return d;
}
__device__ __forceinline__ float rcpa(float x) {
    float y; asm("rcp.approx.f32 %0, %1;" : "=f"(y) : "f"(x)); return y;
}
__device__ __forceinline__ float2 unpack2(u64 v) {
    float2 f; asm("mov.b64 {%0, %1}, %2;" : "=f"(f.x), "=f"(f.y) : "l"(v)); return f;
}
__device__ __forceinline__ u64 packdup(float x) {
    u64 v; asm("mov.b64 %0, {%1, %2};" : "=l"(v) : "f"(x), "f"(x)); return v;
}
__device__ __forceinline__ uint32_t smem_u32(const void* p) {
    return (uint32_t)__cvta_generic_to_shared(p);
}

// ---------------------------------------------------------------------------
// GEMM with f32x2 packed FMA (round-6 mainloop; epilogue scatters to the
// interleaved xg layout).  xg[row, j, gate] = sum_i X[row,i]*W[gate*256+j, i]
// ---------------------------------------------------------------------------
__global__ void __launch_bounds__(256)
gemm_xg_kernel(const float* __restrict__ X, long lda,
               const float* __restrict__ W, const float* __restrict__ bias)
{
    __shared__ alignas(16) float As[16][132];
    __shared__ alignas(16) float Bs[16][68];

    const int t   = threadIdx.x;
    const int tx  = t & 15;
    const int ty  = t >> 4;
    const int r0  = blockIdx.y * 128;
    const int g0  = blockIdx.x * 64;

    const int arow = t >> 2;
    const int ak   = (t & 3) * 4;

    u64 acc2[4][4];
#pragma unroll
    for (int i = 0; i < 4; i++)
#pragma unroll
        for (int j = 0; j < 4; j++) acc2[i][j] = 0ull;

    for (int kt = 0; kt < 16; kt++) {
        const int k0 = kt * 16;
        float4 a0 = *reinterpret_cast<const float4*>(X + (size_t)(r0 + arow) * lda + k0 + ak);
        float4 a1 = *reinterpret_cast<const float4*>(X + (size_t)(r0 + arow + 64) * lda + k0 + ak);
        As[ak + 0][arow] = a0.x; As[ak + 1][arow] = a0.y;
        As[ak + 2][arow] = a0.z; As[ak + 3][arow] = a0.w;
        As[ak + 0][arow + 64] = a1.x; As[ak + 1][arow + 64] = a1.y;
        As[ak + 2][arow + 64] = a1.z; As[ak + 3][arow + 64] = a1.w;
        float4 bv = *reinterpret_cast<const float4*>(W + (size_t)(g0 + arow) * 256 + k0 + ak);
        Bs[ak + 0][arow] = bv.x; Bs[ak + 1][arow] = bv.y;
        Bs[ak + 2][arow] = bv.z; Bs[ak + 3][arow] = bv.w;
        __syncthreads();

#pragma unroll
        for (int kk = 0; kk < 16; kk++) {
            const u64* ap = reinterpret_cast<const u64*>(&As[kk][ty * 8]);
            u64 pa0 = ap[0], pa1 = ap[1], pa2 = ap[2], pa3 = ap[3];
            float4 bv4 = *reinterpret_cast<const float4*>(&Bs[kk][tx * 4]);
            u64 pb0 = packdup(bv4.x), pb1 = packdup(bv4.y);
            u64 pb2 = packdup(bv4.z), pb3 = packdup(bv4.w);
            acc2[0][0] = ffma2(pa0, pb0, acc2[0][0]);
            acc2[0][1] = ffma2(pa0, pb1, acc2[0][1]);
            acc2[0][2] = ffma2(pa0, pb2, acc2[0][2]);
            acc2[0][3] = ffma2(pa0, pb3, acc2[0][3]);
            acc2[1][0] = ffma2(pa1, pb0, acc2[1][0]);
            acc2[1][1] = ffma2(pa1, pb1, acc2[1][1]);
            acc2[1][2] = ffma2(pa1, pb2, acc2[1][2]);
            acc2[1][3] = ffma2(pa1, pb3, acc2[1][3]);
            acc2[2][0] = ffma2(pa2, pb0, acc2[2][0]);
            acc2[2][1] = ffma2(pa2, pb1, acc2[2][1]);
            acc2[2][2] = ffma2(pa2, pb2, acc2[2][2]);
            acc2[2][3] = ffma2(pa2, pb3, acc2[2][3]);
            acc2[3][0] = ffma2(pa3, pb0, acc2[3][0]);
            acc2[3][1] = ffma2(pa3, pb1, acc2[3][1]);
            acc2[3][2] = ffma2(pa3, pb2, acc2[3][2]);
            acc2[3][3] = ffma2(pa3, pb3, acc2[3][3]);
        }
        __syncthreads();
    }

    float4 b4 = *reinterpret_cast<const float4*>(bias + g0 + tx * 4);
    const float bb[4] = {b4.x, b4.y, b4.z, b4.w};
#pragma unroll
    for (int i = 0; i < 4; i++) {
#pragma unroll
        for (int jj = 0; jj < 4; jj++) {
            float2 cp = unpack2(acc2[i][jj]);
            const int g    = g0 + tx * 4 + jj;
            const int unit = g & 255;
            const int gate = g >> 8;
            size_t row0 = (size_t)(r0 + ty * 8 + 2 * i);
            g_xg[row0 * 1024 + unit * 4 + gate]       = cp.x + bb[jj];
            g_xg[(row0 + 1) * 1024 + unit * 4 + gate] = cp.y + bb[jj];
        }
    }
}

// ---------------------------------------------------------------------------
// Persistent GRU scan — round-6 structure (proven best) with:
//  - immediate-offset LDS (one base reg per step, constant offsets)
//  - interleaved xg: one LDG.128 per leader per sb per step
//  - HAS_OUT2 compile-time flag
// ---------------------------------------------------------------------------
template <bool HAS_OUT2>
__global__ void __cluster_dims__(4, 1, 1) __launch_bounds__(512, 1)
gru_scan_kernel(const float* __restrict__ Whh,   // [768,256]
                const float* __restrict__ bhh,   // [768]
                float* __restrict__ out, int ostride,
                float* __restrict__ out2, int ostride2)
{
    __shared__ alignas(16) float rbuf[2][4][2][64];  // [parity][rank][sb][unit]
    __shared__ alignas(8)  u64   mbars[2];

    const int c    = blockIdx.x;               // cluster rank
    const int tid  = threadIdx.x;
    const int warp = tid >> 5;
    const int lane = tid & 31;
    const int ul   = warp * 4 + (lane >> 3);   // local unit 0..63
    const int jg   = c * 64 + ul;              // global hidden unit
    const int kc   = lane & 7;                 // k-slice id
    const bool leader = kc == 0;
    const int b0   = blockIdx.y * 2;

    // weights, interleaved-k order: thread kc owns k = 32*i + 4*kc .. +3
    u64 wr2[16], wz2[16], wn2[16];
#pragma unroll
    for (int i = 0; i < 8; i++) {
        const int k4 = 32 * i + 4 * kc;
        wr2[2*i]   = *reinterpret_cast<const u64*>(Whh + (size_t)jg * HH + k4);
        wr2[2*i+1] = *reinterpret_cast<const u64*>(Whh + (size_t)jg * HH + k4 + 2);
        wz2[2*i]   = *reinterpret_cast<const u64*>(Whh + (size_t)(256 + jg) * HH + k4);
        wz2[2*i+1] = *reinterpret_cast<const u64*>(Whh + (size_t)(256 + jg) * HH + k4 + 2);
        wn2[2*i]   = *reinterpret_cast<const u64*>(Whh + (size_t)(512 + jg) * HH + k4);
        wn2[2*i+1] = *reinterpret_cast<const u64*>(Whh + (size_t)(512 + jg) * HH + k4 + 2);
    }
    float bhr = 0.f, bhz = 0.f, bhn = 0.f;
    if (leader) { bhr = bhh[jg]; bhz = bhh[256 + jg]; bhn = bhh[512 + jg]; }

    // zero parity-0 buffer (512 floats)
    ((float*)rbuf)[tid] = 0.f;
    const uint32_t mb = smem_u32(mbars);
    const uint32_t hb = smem_u32(rbuf);
    if (tid == 0) {
        asm volatile("mbarrier.init.shared.b64 [%0], 1;" :: "r"(mb)     : "memory");
        asm volatile("mbarrier.init.shared.b64 [%0], 1;" :: "r"(mb + 8) : "memory");
    }
    __syncthreads();
    asm volatile("barrier.cluster.arrive.aligned;" ::: "memory");
    asm volatile("barrier.cluster.wait.aligned;"   ::: "memory");

    // hoisted per-rank remote bases
    uint32_t hb_r[4], mb_r[4];
#pragma unroll
    for (int r = 0; r < 4; r++) {
        asm volatile("mapa.shared::cluster.u32 %0, %1, %2;" : "=r"(hb_r[r]) : "r"(hb), "r"(r));
        asm volatile("mapa.shared::cluster.u32 %0, %1, %2;" : "=r"(mb_r[r]) : "r"(mb), "r"(r));
    }

    // xg prefetch for t=0 (leaders): one float4 per sb (r,z,n in .x/.y/.z)
    float4 xp[2];
    if (leader) {
#pragma unroll
        for (int sb = 0; sb < 2; sb++) {
            size_t row = (size_t)(b0 + sb) * SS;
            xp[sb] = *reinterpret_cast<const float4*>(&g_xg[row * 1024 + jg * 4]);
        }
    }

    const float* hb_f = &rbuf[0][0][0][0];
    const int    bofs_base = 4 * kc;            // float offset of this lane's k-slice
    const int hrank = jg >> 6, hidx = jg & 63;
    int ph0 = 0, ph1 = 0;

    for (int t = 0; t < SS; t++) {
        const int p = t & 1, pq = p ^ 1;
        if (tid == 0) {
            asm volatile("mbarrier.arrive.expect_tx.shared.b64 _, [%0], %1;"
                         :: "r"(mb + pq * 8), "r"(1536u) : "memory");
        }
        float4 x4[2];
        if (leader) {
            x4[0] = xp[0]; x4[1] = xp[1];
            const int tn = (t + 1 < SS) ? t + 1 : t;
#pragma unroll
            for (int sb = 0; sb < 2; sb++) {
                size_t row = (size_t)(b0 + sb) * SS + tn;
                xp[sb] = *reinterpret_cast<const float4*>(&g_xg[row * 1024 + jg * 4]);
            }
        }

        // single base pointer for this step's parity; all loads use const offsets
        const float* hpB = hb_f + (p ? 512 : 0) + bofs_base;

#pragma unroll
        for (int sb = 0; sb < 2; sb++) {
            u64 aR = 0ull, aZ = 0ull, aN = 0ull;
#pragma unroll
            for (int i = 0; i < 8; i++) {
                // float offset: (i>>1)*128 (rank) + (i&1)*32 + sb*64  — compile-time
                const int IMM = (i >> 1) * 128 + (i & 1) * 32 + sb * 64;
                ulonglong2 hv = *reinterpret_cast<const ulonglong2*>(hpB + IMM);
                aR = ffma2(wr2[2*i],   hv.x, aR);
                aZ = ffma2(wz2[2*i],   hv.x, aZ);
                aN = ffma2(wn2[2*i],   hv.x, aN);
                aR = ffma2(wr2[2*i+1], hv.y, aR);
                aZ = ffma2(wz2[2*i+1], hv.y, aZ);
                aN = ffma2(wn2[2*i+1], hv.y, aN);
            }
            float2 fR = unpack2(aR), fZ = unpack2(aZ), fN = unpack2(aN);
            float sR = fR.x + fR.y, sZ = fZ.x + fZ.y, sN = fN.x + fN.y;
#pragma unroll
            for (int d = 4; d; d >>= 1) {
                sR += __shfl_down_sync(0xffffffffu, sR, d);
                sZ += __shfl_down_sync(0xffffffffu, sZ, d);
                sN += __shfl_down_sync(0xffffffffu, sN, d);
            }
            if (leader) {
                float er = __expf(-(x4[sb].x + sR + bhr));
                float r  = rcpa(1.f + er);
                float ez = __expf(-(x4[sb].y + sZ + bhz));
                float z  = rcpa(1.f + ez);
                float na = x4[sb].z + r * (sN + bhn);
                float en = __expf(-2.f * na);
                float n  = (1.f - en) * rcpa(1.f + en);
                float hold = rbuf[p][hrank][sb][hidx];
                float hnew = n + z * (hold - n);

                size_t row = (size_t)(b0 + sb) * SS + t;
                out[row * ostride + jg] = hnew;
                if (HAS_OUT2) out2[row * ostride2 + jg] = hnew;

                rbuf[pq][c][sb][ul] = hnew;   // local write of own slice
            }
        }
        __syncthreads();

        // ship own 512B slice to the 3 other ranks as bulk DMA
        if (tid == 0) {
            asm volatile("fence.proxy.async.shared::cta;" ::: "memory");
            const uint32_t off = (uint32_t)(pq * 2048 + c * 512);
            const uint32_t src = hb + off;
#pragma unroll
            for (int r = 0; r < 4; r++) {
                if (r != c) {
                    asm volatile(
                        "cp.async.bulk.shared::cluster.shared::cta.mbarrier::complete_tx::bytes "
                        "[%0], [%1], %2, [%3];"
                        :: "r"(hb_r[r] + off), "r"(src), "r"(512u),
                           "r"(mb_r[r] + (uint32_t)(pq * 8)) : "memory");
                }
            }
        }

        // wait for the 3 remote slices of step t+1
        {
            uint32_t maddr = mb + pq * 8;
            uint32_t parity = pq ? ph1 : ph0;
            uint32_t done;
            asm volatile(
                "{\n\t.reg .pred p;\n\t"
                "mbarrier.try_wait.parity.acquire.cta.shared::cta.b64 p, [%1], %2;\n\t"
                "selp.b32 %0, 1, 0, p;\n\t}"
                : "=r"(done) : "r"(maddr), "r"(parity) : "memory");
            if (!done) {
                asm volatile(
                    "{\n\t.reg .pred P1;\n\t"
                    "WL_%=:\n\t"
                    "mbarrier.try_wait.parity.acquire.cta.shared::cta.b64 P1, [%0], %1, 0x989680;\n\t"
                    "@P1 bra.uni WD_%=;\n\t"
                    "bra.uni WL_%=;\n\t"
                    "WD_%=:\n\t}"
                    :: "r"(maddr), "r"(parity) : "memory");
            }
            if (pq) ph1 ^= 1; else ph0 ^= 1;
        }
    }
}

// ---------------------------------------------------------------------------
extern "C" void kernel_launch(void* const* d_in, const int* in_sizes, int n_in,
                              void* d_out, int out_size)
{
    (void)in_sizes; (void)n_in; (void)out_size;
    const float* inputs = (const float*)d_in[0];
    const float* W_ih0  = (const float*)d_in[1];
    const float* W_hh0  = (const float*)d_in[2];
    const float* b_ih0  = (const float*)d_in[3];
    const float* b_hh0  = (const float*)d_in[4];
    const float* W_ih1  = (const float*)d_in[5];
    const float* W_hh1  = (const float*)d_in[6];
    const float* b_ih1  = (const float*)d_in[7];
    const float* b_hh1  = (const float*)d_in[8];

    float* out    = (float*)d_out;
    float* h2     = out;                               // [B,S,H]
    float* concat = out + (size_t)BB * SS * HH;        // [B,S,2H]

    dim3 gemm_grid(G3 / 64, (BB * SS) / 128);
    dim3 scan_grid(4, BB / 2);

    // Layer 0
    gemm_xg_kernel<<<gemm_grid, 256>>>(inputs, (long)II, W_ih0, b_ih0);
    gru_scan_kernel<false><<<scan_grid, 512>>>(W_hh0, b_hh0, concat, 2 * HH, nullptr, 0);

    // Layer 1 (reads h1 from concat, lda = 512)
    gemm_xg_kernel<<<gemm_grid, 256>>>(concat, (long)(2 * HH), W_ih1, b_ih1);
    gru_scan_kernel<true><<<scan_grid, 512>>>(W_hh1, b_hh1, concat + HH, 2 * HH, h2, HH);
}

// round 14
// speedup vs baseline: 1.0276x; 1.0276x over previous
#include <cuda_runtime.h>
#include <cstdint>

#define BB   64
#define SS   1024
#define II   256
#define HH   256
#define G3   768

typedef unsigned long long u64;

// Scratch for input-side gate projections: [B*S, 768] fp32
__device__ float g_xg[(size_t)BB * SS * G3];

__device__ __forceinline__ u64 ffma2(u64 a, u64 b, u64 c) {
    u64 d; asm("fma.rn.f32x2 %0, %1, %2, %3;" : "=l"(d) : "l"(a), "l"(b), "l"(c)); return d;
}
__device__ __forceinline__ float rcpa(float x) {
    float y; asm("rcp.approx.f32 %0, %1;" : "=f"(y) : "f"(x)); return y;
}
__device__ __forceinline__ float2 unpack2(u64 v) {
    float2 f; asm("mov.b64 {%0, %1}, %2;" : "=f"(f.x), "=f"(f.y) : "l"(v)); return f;
}
__device__ __forceinline__ u64 packdup(float x) {
    u64 v; asm("mov.b64 %0, {%1, %2};" : "=l"(v) : "f"(x), "f"(x)); return v;
}
__device__ __forceinline__ uint32_t smem_u32(const void* p) {
    return (uint32_t)__cvta_generic_to_shared(p);
}
// mbarrier parity wait (try fast path, then poll)
__device__ __forceinline__ void mbar_wait(uint32_t maddr, uint32_t parity) {
    uint32_t done;
    asm volatile(
        "{\n\t.reg .pred p;\n\t"
        "mbarrier.try_wait.parity.acquire.cta.shared::cta.b64 p, [%1], %2;\n\t"
        "selp.b32 %0, 1, 0, p;\n\t}"
        : "=r"(done) : "r"(maddr), "r"(parity) : "memory");
    if (!done) {
        asm volatile(
            "{\n\t.reg .pred P1;\n\t"
            "WL_%=:\n\t"
            "mbarrier.try_wait.parity.acquire.cta.shared::cta.b64 P1, [%0], %1, 0x989680;\n\t"
            "@P1 bra.uni WD_%=;\n\t"
            "bra.uni WL_%=;\n\t"
            "WD_%=:\n\t}"
            :: "r"(maddr), "r"(parity) : "memory");
    }
}

// ---------------------------------------------------------------------------
// GEMM with f32x2 packed FMA (round-6 version, passing).
// ---------------------------------------------------------------------------
__global__ void __launch_bounds__(256)
gemm_xg_kernel(const float* __restrict__ X, long lda,
               const float* __restrict__ W, const float* __restrict__ bias)
{
    __shared__ alignas(16) float As[16][132];
    __shared__ alignas(16) float Bs[16][68];

    const int t   = threadIdx.x;
    const int tx  = t & 15;
    const int ty  = t >> 4;
    const int r0  = blockIdx.y * 128;
    const int g0  = blockIdx.x * 64;

    const int arow = t >> 2;
    const int ak   = (t & 3) * 4;

    u64 acc2[4][4];
#pragma unroll
    for (int i = 0; i < 4; i++)
#pragma unroll
        for (int j = 0; j < 4; j++) acc2[i][j] = 0ull;

    for (int kt = 0; kt < 16; kt++) {
        const int k0 = kt * 16;
        float4 a0 = *reinterpret_cast<const float4*>(X + (size_t)(r0 + arow) * lda + k0 + ak);
        float4 a1 = *reinterpret_cast<const float4*>(X + (size_t)(r0 + arow + 64) * lda + k0 + ak);
        As[ak + 0][arow] = a0.x; As[ak + 1][arow] = a0.y;
        As[ak + 2][arow] = a0.z; As[ak + 3][arow] = a0.w;
        As[ak + 0][arow + 64] = a1.x; As[ak + 1][arow + 64] = a1.y;
        As[ak + 2][arow + 64] = a1.z; As[ak + 3][arow + 64] = a1.w;
        float4 bv = *reinterpret_cast<const float4*>(W + (size_t)(g0 + arow) * 256 + k0 + ak);
        Bs[ak + 0][arow] = bv.x; Bs[ak + 1][arow] = bv.y;
        Bs[ak + 2][arow] = bv.z; Bs[ak + 3][arow] = bv.w;
        __syncthreads();

#pragma unroll
        for (int kk = 0; kk < 16; kk++) {
            const u64* ap = reinterpret_cast<const u64*>(&As[kk][ty * 8]);
            u64 pa0 = ap[0], pa1 = ap[1], pa2 = ap[2], pa3 = ap[3];
            float4 bv4 = *reinterpret_cast<const float4*>(&Bs[kk][tx * 4]);
            u64 pb0 = packdup(bv4.x), pb1 = packdup(bv4.y);
            u64 pb2 = packdup(bv4.z), pb3 = packdup(bv4.w);
            acc2[0][0] = ffma2(pa0, pb0, acc2[0][0]);
            acc2[0][1] = ffma2(pa0, pb1, acc2[0][1]);
            acc2[0][2] = ffma2(pa0, pb2, acc2[0][2]);
            acc2[0][3] = ffma2(pa0, pb3, acc2[0][3]);
            acc2[1][0] = ffma2(pa1, pb0, acc2[1][0]);
            acc2[1][1] = ffma2(pa1, pb1, acc2[1][1]);
            acc2[1][2] = ffma2(pa1, pb2, acc2[1][2]);
            acc2[1][3] = ffma2(pa1, pb3, acc2[1][3]);
            acc2[2][0] = ffma2(pa2, pb0, acc2[2][0]);
            acc2[2][1] = ffma2(pa2, pb1, acc2[2][1]);
            acc2[2][2] = ffma2(pa2, pb2, acc2[2][2]);
            acc2[2][3] = ffma2(pa2, pb3, acc2[2][3]);
            acc2[3][0] = ffma2(pa3, pb0, acc2[3][0]);
            acc2[3][1] = ffma2(pa3, pb1, acc2[3][1]);
            acc2[3][2] = ffma2(pa3, pb2, acc2[3][2]);
            acc2[3][3] = ffma2(pa3, pb3, acc2[3][3]);
        }
        __syncthreads();
    }

    float4 b4 = *reinterpret_cast<const float4*>(bias + g0 + tx * 4);
#pragma unroll
    for (int i = 0; i < 4; i++) {
        float2 c0 = unpack2(acc2[i][0]), c1 = unpack2(acc2[i][1]);
        float2 c2 = unpack2(acc2[i][2]), c3 = unpack2(acc2[i][3]);
        size_t row0 = (size_t)(r0 + ty * 8 + 2 * i);
        float4 v0, v1;
        v0.x = c0.x + b4.x; v0.y = c1.x + b4.y; v0.z = c2.x + b4.z; v0.w = c3.x + b4.w;
        v1.x = c0.y + b4.x; v1.y = c1.y + b4.y; v1.z = c2.y + b4.z; v1.w = c3.y + b4.w;
        *reinterpret_cast<float4*>(&g_xg[row0 * G3 + g0 + tx * 4]) = v0;
        *reinterpret_cast<float4*>(&g_xg[(row0 + 1) * G3 + g0 + tx * 4]) = v1;
    }
}

// ---------------------------------------------------------------------------
// Persistent GRU scan — round-6 compute, STAGGERED batch slots:
//   wait(sb0) -> compute sb0 -> ship sb0 -> wait(sb1) -> compute sb1 -> ship sb1
// Each slot's DSMEM flight is hidden behind the other slot's compute.
// Per-sb double-buffered mbarriers (expect_tx = 3 x 256B).
// ---------------------------------------------------------------------------
__global__ void __cluster_dims__(4, 1, 1) __launch_bounds__(512, 1)
gru_scan_kernel(const float* __restrict__ Whh,   // [768,256]
                const float* __restrict__ bhh,   // [768]
                float* __restrict__ out, int ostride,
                float* __restrict__ out2, int ostride2)  // may be null
{
    __shared__ alignas(16) float rbuf[2][2][4][64];  // [sb][parity][rank][unit]
    __shared__ alignas(8)  u64   mbars[4];           // [sb*2 + parity]

    const int c    = blockIdx.x;               // cluster rank
    const int tid  = threadIdx.x;
    const int warp = tid >> 5;
    const int lane = tid & 31;
    const int ul   = warp * 4 + (lane >> 3);   // local unit 0..63
    const int jg   = c * 64 + ul;              // global hidden unit
    const int kc   = lane & 7;                 // k-slice id
    const bool leader = kc == 0;
    const int b0   = blockIdx.y * 2;

    // weights, interleaved-k order: thread kc owns k = 32*i + 4*kc .. +3
    u64 wr2[16], wz2[16], wn2[16];
#pragma unroll
    for (int i = 0; i < 8; i++) {
        const int k4 = 32 * i + 4 * kc;
        wr2[2*i]   = *reinterpret_cast<const u64*>(Whh + (size_t)jg * HH + k4);
        wr2[2*i+1] = *reinterpret_cast<const u64*>(Whh + (size_t)jg * HH + k4 + 2);
        wz2[2*i]   = *reinterpret_cast<const u64*>(Whh + (size_t)(256 + jg) * HH + k4);
        wz2[2*i+1] = *reinterpret_cast<const u64*>(Whh + (size_t)(256 + jg) * HH + k4 + 2);
        wn2[2*i]   = *reinterpret_cast<const u64*>(Whh + (size_t)(512 + jg) * HH + k4);
        wn2[2*i+1] = *reinterpret_cast<const u64*>(Whh + (size_t)(512 + jg) * HH + k4 + 2);
    }
    float bhr = 0.f, bhz = 0.f, bhn = 0.f;
    if (leader) { bhr = bhh[jg]; bhz = bhh[256 + jg]; bhn = bhh[512 + jg]; }

    // zero parity-0 buffers of both sb: flat idx = sb*512 + [0,256)
    ((float*)rbuf)[(tid >> 8) * 512 + (tid & 255)] = 0.f;
    const uint32_t mb = smem_u32(mbars);
    const uint32_t hb = smem_u32(rbuf);
    if (tid == 0) {
#pragma unroll
        for (int q = 0; q < 4; q++)
            asm volatile("mbarrier.init.shared.b64 [%0], 1;" :: "r"(mb + q * 8) : "memory");
    }
    __syncthreads();
    asm volatile("barrier.cluster.arrive.aligned;" ::: "memory");
    asm volatile("barrier.cluster.wait.aligned;"   ::: "memory");

    // hoisted per-rank remote bases
    uint32_t hb_r[4], mb_r[4];
#pragma unroll
    for (int r = 0; r < 4; r++) {
        asm volatile("mapa.shared::cluster.u32 %0, %1, %2;" : "=r"(hb_r[r]) : "r"(hb), "r"(r));
        asm volatile("mapa.shared::cluster.u32 %0, %1, %2;" : "=r"(mb_r[r]) : "r"(mb), "r"(r));
    }

    // xg prefetch for t=0 (leaders)
    float xpr[2], xpz[2], xpn[2];
    if (leader) {
#pragma unroll
        for (int sb = 0; sb < 2; sb++) {
            size_t base = ((size_t)(b0 + sb) * SS) * G3;
            xpr[sb] = __ldg(&g_xg[base + jg]);
            xpz[sb] = __ldg(&g_xg[base + 256 + jg]);
            xpn[sb] = __ldg(&g_xg[base + 512 + jg]);
        }
    }

    const int hrank = jg >> 6, hidx = jg & 63;
    // phases: [sb][parity] tracked as scalars to avoid local-mem arrays
    int ph00 = 0, ph01 = 0, ph10 = 0, ph11 = 0;

    for (int t = 0; t < SS; t++) {
        const int p = t & 1, pq = p ^ 1;
        const bool not_last = (t + 1 < SS);

        if (tid == 0 && not_last) {
            // arm both sb receive barriers for step t+1 data (3 x 256B each)
            asm volatile("mbarrier.arrive.expect_tx.shared.b64 _, [%0], %1;"
                         :: "r"(mb + (0 * 2 + pq) * 8), "r"(768u) : "memory");
            asm volatile("mbarrier.arrive.expect_tx.shared.b64 _, [%0], %1;"
                         :: "r"(mb + (1 * 2 + pq) * 8), "r"(768u) : "memory");
        }
        float xr[2], xz[2], xn[2];
        if (leader) {
#pragma unroll
            for (int sb = 0; sb < 2; sb++) { xr[sb]=xpr[sb]; xz[sb]=xpz[sb]; xn[sb]=xpn[sb]; }
            const int tn = not_last ? t + 1 : t;
#pragma unroll
            for (int sb = 0; sb < 2; sb++) {
                size_t base = ((size_t)(b0 + sb) * SS + tn) * G3;
                xpr[sb] = __ldg(&g_xg[base + jg]);
                xpz[sb] = __ldg(&g_xg[base + 256 + jg]);
                xpn[sb] = __ldg(&g_xg[base + 512 + jg]);
            }
        }

#pragma unroll
        for (int sb = 0; sb < 2; sb++) {
            // wait for this slot's step-t data (skipped at t=0)
            if (t) {
                uint32_t maddr = mb + (sb * 2 + p) * 8;
                uint32_t parity = sb ? (p ? ph11 : ph10) : (p ? ph01 : ph00);
                mbar_wait(maddr, parity);
                if (sb) { if (p) ph11 ^= 1; else ph10 ^= 1; }
                else    { if (p) ph01 ^= 1; else ph00 ^= 1; }
            }

            // ---- round-6 compute, verbatim (address layout [sb][p][rank]) ----
            u64 aR = 0ull, aZ = 0ull, aN = 0ull;
#pragma unroll
            for (int i = 0; i < 8; i++) {
                const int k4 = 32 * i + 4 * kc;
                ulonglong2 hv = *reinterpret_cast<const ulonglong2*>(
                    &rbuf[sb][p][k4 >> 6][k4 & 63]);
                aR = ffma2(wr2[2*i],   hv.x, aR);
                aZ = ffma2(wz2[2*i],   hv.x, aZ);
                aN = ffma2(wn2[2*i],   hv.x, aN);
                aR = ffma2(wr2[2*i+1], hv.y, aR);
                aZ = ffma2(wz2[2*i+1], hv.y, aZ);
                aN = ffma2(wn2[2*i+1], hv.y, aN);
            }
            float2 fR = unpack2(aR), fZ = unpack2(aZ), fN = unpack2(aN);
            float sR = fR.x + fR.y, sZ = fZ.x + fZ.y, sN = fN.x + fN.y;
#pragma unroll
            for (int d = 4; d; d >>= 1) {
                sR += __shfl_down_sync(0xffffffffu, sR, d);
                sZ += __shfl_down_sync(0xffffffffu, sZ, d);
                sN += __shfl_down_sync(0xffffffffu, sN, d);
            }
            if (leader) {
                float er = __expf(-(xr[sb] + sR + bhr));
                float r  = rcpa(1.f + er);
                float ez = __expf(-(xz[sb] + sZ + bhz));
                float z  = rcpa(1.f + ez);
                float na = xn[sb] + r * (sN + bhn);
                float en = __expf(-2.f * na);
                float n  = (1.f - en) * rcpa(1.f + en);
                float hold = rbuf[sb][p][hrank][hidx];
                float hnew = n + z * (hold - n);

                size_t row = (size_t)(b0 + sb) * SS + t;
                out[row * ostride + jg] = hnew;
                if (out2) out2[row * ostride2 + jg] = hnew;

                rbuf[sb][pq][c][ul] = hnew;   // local write of own slice
            }
            __syncthreads();

            // ship this slot's 256B slice to the 3 other ranks
            if (tid == 0 && not_last) {
                asm volatile("fence.proxy.async.shared::cta;" ::: "memory");
                const uint32_t off = (uint32_t)(sb * 2048 + pq * 1024 + c * 256);
                const uint32_t src = hb + off;
                const uint32_t mof = (uint32_t)((sb * 2 + pq) * 8);
#pragma unroll
                for (int r = 0; r < 4; r++) {
                    if (r != c) {
                        asm volatile(
                            "cp.async.bulk.shared::cluster.shared::cta.mbarrier::complete_tx::bytes "
                            "[%0], [%1], %2, [%3];"
                            :: "r"(hb_r[r] + off), "r"(src), "r"(256u),
                               "r"(mb_r[r] + mof) : "memory");
                    }
                }
            }
        }
    }
}

// ---------------------------------------------------------------------------
extern "C" void kernel_launch(void* const* d_in, const int* in_sizes, int n_in,
                              void* d_out, int out_size)
{
    (void)in_sizes; (void)n_in; (void)out_size;
    const float* inputs = (const float*)d_in[0];
    const float* W_ih0  = (const float*)d_in[1];
    const float* W_hh0  = (const float*)d_in[2];
    const float* b_ih0  = (const float*)d_in[3];
    const float* b_hh0  = (const float*)d_in[4];
    const float* W_ih1  = (const float*)d_in[5];
    const float* W_hh1  = (const float*)d_in[6];
    const float* b_ih1  = (const float*)d_in[7];
    const float* b_hh1  = (const float*)d_in[8];

    float* out    = (float*)d_out;
    float* h2     = out;                               // [B,S,H]
    float* concat = out + (size_t)BB * SS * HH;        // [B,S,2H]

    dim3 gemm_grid(G3 / 64, (BB * SS) / 128);
    dim3 scan_grid(4, BB / 2);

    // Layer 0
    gemm_xg_kernel<<<gemm_grid, 256>>>(inputs, (long)II, W_ih0, b_ih0);
    gru_scan_kernel<<<scan_grid, 512>>>(W_hh0, b_hh0, concat, 2 * HH, nullptr, 0);

    // Layer 1 (reads h1 from concat, lda = 512)
    gemm_xg_kernel<<<gemm_grid, 256>>>(concat, (long)(2 * HH), W_ih1, b_ih1);
    gru_scan_kernel<<<scan_grid, 512>>>(W_hh1, b_hh1, concat + HH, 2 * HH, h2, HH);
}

// round 15
// speedup vs baseline: 1.0281x; 1.0005x over previous
#include <cuda_runtime.h>
#include <cstdint>

#define BB   64
#define SS   1024
#define II   256
#define HH   256
#define G3   768

typedef unsigned long long u64;

// Scratch for gate projections, padded by one row for clamp-free prefetch
__device__ float g_xg[((size_t)BB * SS + 1) * G3];

__device__ __forceinline__ u64 ffma2(u64 a, u64 b, u64 c) {
    u64 d; asm("fma.rn.f32x2 %0, %1, %2, %3;" : "=l"(d) : "l"(a), "l"(b), "l"(c)); return d;
}
__device__ __forceinline__ float rcpa(float x) {
    float y; asm("rcp.approx.f32 %0, %1;" : "=f"(y) : "f"(x)); return y;
}
__device__ __forceinline__ float2 unpack2(u64 v) {
    float2 f; asm("mov.b64 {%0, %1}, %2;" : "=f"(f.x), "=f"(f.y) : "l"(v)); return f;
}
__device__ __forceinline__ u64 packdup(float x) {
    u64 v; asm("mov.b64 %0, {%1, %2};" : "=l"(v) : "f"(x), "f"(x)); return v;
}
__device__ __forceinline__ uint32_t smem_u32(const void* p) {
    return (uint32_t)__cvta_generic_to_shared(p);
}
__device__ __forceinline__ void mbar_wait(uint32_t maddr, uint32_t parity) {
    uint32_t done;
    asm volatile(
        "{\n\t.reg .pred p;\n\t"
        "mbarrier.try_wait.parity.acquire.cta.shared::cta.b64 p, [%1], %2;\n\t"
        "selp.b32 %0, 1, 0, p;\n\t}"
        : "=r"(done) : "r"(maddr), "r"(parity) : "memory");
    if (!done) {
        asm volatile(
            "{\n\t.reg .pred P1;\n\t"
            "WL_%=:\n\t"
            "mbarrier.try_wait.parity.acquire.cta.shared::cta.b64 P1, [%0], %1, 0x989680;\n\t"
            "@P1 bra.uni WD_%=;\n\t"
            "bra.uni WL_%=;\n\t"
            "WD_%=:\n\t}"
            :: "r"(maddr), "r"(parity) : "memory");
    }
}

// ---------------------------------------------------------------------------
// GEMM with f32x2 packed FMA (round-6 version, passing).
// ---------------------------------------------------------------------------
__global__ void __launch_bounds__(256)
gemm_xg_kernel(const float* __restrict__ X, long lda,
               const float* __restrict__ W, const float* __restrict__ bias)
{
    __shared__ alignas(16) float As[16][132];
    __shared__ alignas(16) float Bs[16][68];

    const int t   = threadIdx.x;
    const int tx  = t & 15;
    const int ty  = t >> 4;
    const int r0  = blockIdx.y * 128;
    const int g0  = blockIdx.x * 64;

    const int arow = t >> 2;
    const int ak   = (t & 3) * 4;

    u64 acc2[4][4];
#pragma unroll
    for (int i = 0; i < 4; i++)
#pragma unroll
        for (int j = 0; j < 4; j++) acc2[i][j] = 0ull;

    for (int kt = 0; kt < 16; kt++) {
        const int k0 = kt * 16;
        float4 a0 = *reinterpret_cast<const float4*>(X + (size_t)(r0 + arow) * lda + k0 + ak);
        float4 a1 = *reinterpret_cast<const float4*>(X + (size_t)(r0 + arow + 64) * lda + k0 + ak);
        As[ak + 0][arow] = a0.x; As[ak + 1][arow] = a0.y;
        As[ak + 2][arow] = a0.z; As[ak + 3][arow] = a0.w;
        As[ak + 0][arow + 64] = a1.x; As[ak + 1][arow + 64] = a1.y;
        As[ak + 2][arow + 64] = a1.z; As[ak + 3][arow + 64] = a1.w;
        float4 bv = *reinterpret_cast<const float4*>(W + (size_t)(g0 + arow) * 256 + k0 + ak);
        Bs[ak + 0][arow] = bv.x; Bs[ak + 1][arow] = bv.y;
        Bs[ak + 2][arow] = bv.z; Bs[ak + 3][arow] = bv.w;
        __syncthreads();

#pragma unroll
        for (int kk = 0; kk < 16; kk++) {
            const u64* ap = reinterpret_cast<const u64*>(&As[kk][ty * 8]);
            u64 pa0 = ap[0], pa1 = ap[1], pa2 = ap[2], pa3 = ap[3];
            float4 bv4 = *reinterpret_cast<const float4*>(&Bs[kk][tx * 4]);
            u64 pb0 = packdup(bv4.x), pb1 = packdup(bv4.y);
            u64 pb2 = packdup(bv4.z), pb3 = packdup(bv4.w);
            acc2[0][0] = ffma2(pa0, pb0, acc2[0][0]);
            acc2[0][1] = ffma2(pa0, pb1, acc2[0][1]);
            acc2[0][2] = ffma2(pa0, pb2, acc2[0][2]);
            acc2[0][3] = ffma2(pa0, pb3, acc2[0][3]);
            acc2[1][0] = ffma2(pa1, pb0, acc2[1][0]);
            acc2[1][1] = ffma2(pa1, pb1, acc2[1][1]);
            acc2[1][2] = ffma2(pa1, pb2, acc2[1][2]);
            acc2[1][3] = ffma2(pa1, pb3, acc2[1][3]);
            acc2[2][0] = ffma2(pa2, pb0, acc2[2][0]);
            acc2[2][1] = ffma2(pa2, pb1, acc2[2][1]);
            acc2[2][2] = ffma2(pa2, pb2, acc2[2][2]);
            acc2[2][3] = ffma2(pa2, pb3, acc2[2][3]);
            acc2[3][0] = ffma2(pa3, pb0, acc2[3][0]);
            acc2[3][1] = ffma2(pa3, pb1, acc2[3][1]);
            acc2[3][2] = ffma2(pa3, pb2, acc2[3][2]);
            acc2[3][3] = ffma2(pa3, pb3, acc2[3][3]);
        }
        __syncthreads();
    }

    float4 b4 = *reinterpret_cast<const float4*>(bias + g0 + tx * 4);
#pragma unroll
    for (int i = 0; i < 4; i++) {
        float2 c0 = unpack2(acc2[i][0]), c1 = unpack2(acc2[i][1]);
        float2 c2 = unpack2(acc2[i][2]), c3 = unpack2(acc2[i][3]);
        size_t row0 = (size_t)(r0 + ty * 8 + 2 * i);
        float4 v0, v1;
        v0.x = c0.x + b4.x; v0.y = c1.x + b4.y; v0.z = c2.x + b4.z; v0.w = c3.x + b4.w;
        v1.x = c0.y + b4.x; v1.y = c1.y + b4.y; v1.z = c2.y + b4.z; v1.w = c3.y + b4.w;
        *reinterpret_cast<float4*>(&g_xg[row0 * G3 + g0 + tx * 4]) = v0;
        *reinterpret_cast<float4*>(&g_xg[(row0 + 1) * G3 + g0 + tx * 4]) = v1;
    }
}

// ---------------------------------------------------------------------------
// Persistent GRU scan — round-6 structure EXACTLY, t-loop unrolled x2 so the
// buffer parity is a compile-time constant (all smem addresses fold to
// base+immediate), and leader out/xg addressing strength-reduced to
// incremented pointers.  No out2 (separate copy kernel).
// ---------------------------------------------------------------------------

// One scan step with compile-time parity P (read buffer) / PQ (write buffer).
#define GRU_STEP(P, PQ, PHV)                                                   \
    {                                                                          \
        if (tid == 0) {                                                        \
            asm volatile("mbarrier.arrive.expect_tx.shared.b64 _, [%0], %1;"   \
                         :: "r"(mb + (PQ) * 8), "r"(1536u) : "memory");        \
        }                                                                      \
        float xr[2], xz[2], xn[2];                                             \
        if (leader) {                                                          \
            xr[0] = xp0.x; xz[0] = xp0.y; xn[0] = xp0.z;                       \
            xr[1] = xp1.x; xz[1] = xp1.y; xn[1] = xp1.z;                       \
            pxg0 += G3; pxg1 += G3;                                            \
            xp0.x = __ldg(pxg0); xp0.y = __ldg(pxg0 + 256); xp0.z = __ldg(pxg0 + 512); \
            xp1.x = __ldg(pxg1); xp1.y = __ldg(pxg1 + 256); xp1.z = __ldg(pxg1 + 512); \
        }                                                                      \
        _Pragma("unroll")                                                      \
        for (int sb = 0; sb < 2; sb++) {                                       \
            u64 aR = 0ull, aZ = 0ull, aN = 0ull;                               \
            _Pragma("unroll")                                                  \
            for (int i = 0; i < 8; i++) {                                      \
                const int OFF = (P) * 512 + (i >> 1) * 128 + sb * 64 + (i & 1) * 32; \
                ulonglong2 hv = *reinterpret_cast<const ulonglong2*>(kbase + OFF); \
                aR = ffma2(wr2[2*i],   hv.x, aR);                              \
                aZ = ffma2(wz2[2*i],   hv.x, aZ);                              \
                aN = ffma2(wn2[2*i],   hv.x, aN);                              \
                aR = ffma2(wr2[2*i+1], hv.y, aR);                              \
                aZ = ffma2(wz2[2*i+1], hv.y, aZ);                              \
                aN = ffma2(wn2[2*i+1], hv.y, aN);                              \
            }                                                                  \
            float2 fR = unpack2(aR), fZ = unpack2(aZ), fN = unpack2(aN);       \
            float sR = fR.x + fR.y, sZ = fZ.x + fZ.y, sN = fN.x + fN.y;        \
            _Pragma("unroll")                                                  \
            for (int d = 4; d; d >>= 1) {                                      \
                sR += __shfl_down_sync(0xffffffffu, sR, d);                    \
                sZ += __shfl_down_sync(0xffffffffu, sZ, d);                    \
                sN += __shfl_down_sync(0xffffffffu, sN, d);                    \
            }                                                                  \
            if (leader) {                                                      \
                float er = __expf(-(xr[sb] + sR + bhr));                       \
                float r  = rcpa(1.f + er);                                     \
                float ez = __expf(-(xz[sb] + sZ + bhz));                       \
                float z  = rcpa(1.f + ez);                                     \
                float na = xn[sb] + r * (sN + bhn);                            \
                float en = __expf(-2.f * na);                                  \
                float n  = (1.f - en) * rcpa(1.f + en);                        \
                float hold = holdp[(P) * 512 + sb * 64];                       \
                float hnew = n + z * (hold - n);                               \
                if (sb == 0) { *op0 = hnew; op0 += ostride; }                  \
                else         { *op1 = hnew; op1 += ostride; }                  \
                ownp[(PQ) * 512 + sb * 64] = hnew;                             \
            }                                                                  \
        }                                                                      \
        __syncthreads();                                                       \
        if (tid == 0) {                                                        \
            asm volatile("fence.proxy.async.shared::cta;" ::: "memory");       \
            const uint32_t off = (uint32_t)((PQ) * 2048) + c512;               \
            const uint32_t src = hb + off;                                     \
            _Pragma("unroll")                                                  \
            for (int r = 0; r < 4; r++) {                                      \
                if (r != c) {                                                  \
                    asm volatile(                                              \
                        "cp.async.bulk.shared::cluster.shared::cta.mbarrier::complete_tx::bytes " \
                        "[%0], [%1], %2, [%3];"                                \
                        :: "r"(hb_r[r] + off), "r"(src), "r"(512u),            \
                           "r"(mb_r[r] + (uint32_t)((PQ) * 8)) : "memory");    \
                }                                                              \
            }                                                                  \
        }                                                                      \
        mbar_wait(mb + (PQ) * 8, (PHV));                                       \
        (PHV) ^= 1;                                                            \
    }

__global__ void __cluster_dims__(4, 1, 1) __launch_bounds__(512, 1)
gru_scan_kernel(const float* __restrict__ Whh,   // [768,256]
                const float* __restrict__ bhh,   // [768]
                float* __restrict__ out, int ostride)
{
    __shared__ alignas(16) float rbuf[2][4][2][64];  // [parity][rank][sb][unit]
    __shared__ alignas(8)  u64   mbars[2];

    const int c    = blockIdx.x;               // cluster rank
    const int tid  = threadIdx.x;
    const int warp = tid >> 5;
    const int lane = tid & 31;
    const int ul   = warp * 4 + (lane >> 3);   // local unit 0..63
    const int jg   = c * 64 + ul;              // global hidden unit
    const int kc   = lane & 7;                 // k-slice id
    const bool leader = kc == 0;
    const int b0   = blockIdx.y * 2;

    // weights, interleaved-k order: thread kc owns k = 32*i + 4*kc .. +3
    u64 wr2[16], wz2[16], wn2[16];
#pragma unroll
    for (int i = 0; i < 8; i++) {
        const int k4 = 32 * i + 4 * kc;
        wr2[2*i]   = *reinterpret_cast<const u64*>(Whh + (size_t)jg * HH + k4);
        wr2[2*i+1] = *reinterpret_cast<const u64*>(Whh + (size_t)jg * HH + k4 + 2);
        wz2[2*i]   = *reinterpret_cast<const u64*>(Whh + (size_t)(256 + jg) * HH + k4);
        wz2[2*i+1] = *reinterpret_cast<const u64*>(Whh + (size_t)(256 + jg) * HH + k4 + 2);
        wn2[2*i]   = *reinterpret_cast<const u64*>(Whh + (size_t)(512 + jg) * HH + k4);
        wn2[2*i+1] = *reinterpret_cast<const u64*>(Whh + (size_t)(512 + jg) * HH + k4 + 2);
    }
    float bhr = 0.f, bhz = 0.f, bhn = 0.f;
    if (leader) { bhr = bhh[jg]; bhz = bhh[256 + jg]; bhn = bhh[512 + jg]; }

    ((float*)rbuf)[tid] = 0.f;                 // zero parity-0 buffer
    const uint32_t mb = smem_u32(mbars);
    const uint32_t hb = smem_u32(rbuf);
    if (tid == 0) {
        asm volatile("mbarrier.init.shared.b64 [%0], 1;" :: "r"(mb)     : "memory");
        asm volatile("mbarrier.init.shared.b64 [%0], 1;" :: "r"(mb + 8) : "memory");
    }
    __syncthreads();
    asm volatile("barrier.cluster.arrive.aligned;" ::: "memory");
    asm volatile("barrier.cluster.wait.aligned;"   ::: "memory");

    uint32_t hb_r[4], mb_r[4];
#pragma unroll
    for (int r = 0; r < 4; r++) {
        asm volatile("mapa.shared::cluster.u32 %0, %1, %2;" : "=r"(hb_r[r]) : "r"(hb), "r"(r));
        asm volatile("mapa.shared::cluster.u32 %0, %1, %2;" : "=r"(mb_r[r]) : "r"(mb), "r"(r));
    }

    // hoisted bases (loop-invariant)
    const float* kbase = &rbuf[0][0][0][0] + 4 * kc;        // + P*512 + ... imm
    const float* holdp = &rbuf[0][jg >> 6][0][jg & 63];     // + P*512 + sb*64
    float*       ownp  = &rbuf[0][c][0][ul];                // + PQ*512 + sb*64
    const uint32_t c512 = (uint32_t)(c * 512);

    // leader pointers (strength-reduced)
    const float* pxg0 = &g_xg[((size_t)b0 * SS) * G3 + jg];
    const float* pxg1 = &g_xg[((size_t)(b0 + 1) * SS) * G3 + jg];
    float* op0 = out + ((size_t)b0 * SS) * ostride + jg;
    float* op1 = out + ((size_t)(b0 + 1) * SS) * ostride + jg;

    float3 xp0 = {0.f, 0.f, 0.f}, xp1 = {0.f, 0.f, 0.f};
    if (leader) {
        xp0.x = __ldg(pxg0); xp0.y = __ldg(pxg0 + 256); xp0.z = __ldg(pxg0 + 512);
        xp1.x = __ldg(pxg1); xp1.y = __ldg(pxg1 + 256); xp1.z = __ldg(pxg1 + 512);
    }

    int ph0 = 0, ph1 = 0;

    for (int t2 = 0; t2 < SS / 2; t2++) {
        GRU_STEP(0, 1, ph1);
        GRU_STEP(1, 0, ph0);
    }
}

// ---------------------------------------------------------------------------
// h2 = concat[:, :, 256:512]  (vectorized copy, ~6us)
// ---------------------------------------------------------------------------
__global__ void __launch_bounds__(256)
copy_h2_kernel(const float4* __restrict__ src, float4* __restrict__ dst)
{
    size_t i = (size_t)blockIdx.x * blockDim.x + threadIdx.x;
    size_t row = i >> 6;
    int col = (int)(i & 63);
    dst[row * 64 + col] = src[row * 128 + 64 + col];
}

// ---------------------------------------------------------------------------
extern "C" void kernel_launch(void* const* d_in, const int* in_sizes, int n_in,
                              void* d_out, int out_size)
{
    (void)in_sizes; (void)n_in; (void)out_size;
    const float* inputs = (const float*)d_in[0];
    const float* W_ih0  = (const float*)d_in[1];
    const float* W_hh0  = (const float*)d_in[2];
    const float* b_ih0  = (const float*)d_in[3];
    const float* b_hh0  = (const float*)d_in[4];
    const float* W_ih1  = (const float*)d_in[5];
    const float* W_hh1  = (const float*)d_in[6];
    const float* b_ih1  = (const float*)d_in[7];
    const float* b_hh1  = (const float*)d_in[8];

    float* out    = (float*)d_out;
    float* h2     = out;                               // [B,S,H]
    float* concat = out + (size_t)BB * SS * HH;        // [B,S,2H]

    dim3 gemm_grid(G3 / 64, (BB * SS) / 128);
    dim3 scan_grid(4, BB / 2);

    // Layer 0
    gemm_xg_kernel<<<gemm_grid, 256>>>(inputs, (long)II, W_ih0, b_ih0);
    gru_scan_kernel<<<scan_grid, 512>>>(W_hh0, b_hh0, concat, 2 * HH);

    // Layer 1 (reads h1 from concat, lda = 512)
    gemm_xg_kernel<<<gemm_grid, 256>>>(concat, (long)(2 * HH), W_ih1, b_ih1);
    gru_scan_kernel<<<scan_grid, 512>>>(W_hh1, b_hh1, concat + HH, 2 * HH);

    // h2 output = concat[:, :, 256:512]
    copy_h2_kernel<<<16384, 256>>>((const float4*)concat, (float4*)h2);
}

// round 16
// speedup vs baseline: 1.3644x; 1.3271x over previous
#include <cuda_runtime.h>
#include <cstdint>

#define BB   64
#define SS   1024
#define II   256
#define HH   256
#define G3   768

typedef unsigned long long u64;

// Scratch for input-side gate projections: [B*S, 768] fp32
__device__ float g_xg[(size_t)BB * SS * G3];

__device__ __forceinline__ u64 ffma2(u64 a, u64 b, u64 c) {
    u64 d; asm("fma.rn.f32x2 %0, %1, %2, %3;" : "=l"(d) : "l"(a), "l"(b), "l"(c)); return d;
}
__device__ __forceinline__ float rcpa(float x) {
    float y; asm("rcp.approx.f32 %0, %1;" : "=f"(y) : "f"(x)); return y;
}
__device__ __forceinline__ float2 unpack2(u64 v) {
    float2 f; asm("mov.b64 {%0, %1}, %2;" : "=f"(f.x), "=f"(f.y) : "l"(v)); return f;
}
__device__ __forceinline__ u64 packdup(float x) {
    u64 v; asm("mov.b64 %0, {%1, %2};" : "=l"(v) : "f"(x), "f"(x)); return v;
}
__device__ __forceinline__ uint32_t smem_u32(const void* p) {
    return (uint32_t)__cvta_generic_to_shared(p);
}

// ---------------------------------------------------------------------------
// GEMM with f32x2 packed FMA — round-6 math, DOUBLE-BUFFERED K tiles:
// next tile's LDGs issue before current tile's compute; STS to the alternate
// buffer after compute; one __syncthreads per tile. LDG latency hidden.
// ---------------------------------------------------------------------------
__global__ void __launch_bounds__(256)
gemm_xg_kernel(const float* __restrict__ X, long lda,
               const float* __restrict__ W, const float* __restrict__ bias)
{
    __shared__ alignas(16) float As[2][16][132];
    __shared__ alignas(16) float Bs[2][16][68];

    const int t   = threadIdx.x;
    const int tx  = t & 15;
    const int ty  = t >> 4;
    const int r0  = blockIdx.y * 128;
    const int g0  = blockIdx.x * 64;

    const int arow = t >> 2;
    const int ak   = (t & 3) * 4;

    const float* pA0 = X + (size_t)(r0 + arow) * lda + ak;
    const float* pA1 = X + (size_t)(r0 + arow + 64) * lda + ak;
    const float* pB  = W + (size_t)(g0 + arow) * 256 + ak;

    u64 acc2[4][4];
#pragma unroll
    for (int i = 0; i < 4; i++)
#pragma unroll
        for (int j = 0; j < 4; j++) acc2[i][j] = 0ull;

    // prologue: tile 0 -> buffer 0
    {
        float4 a0 = *reinterpret_cast<const float4*>(pA0);
        float4 a1 = *reinterpret_cast<const float4*>(pA1);
        float4 bv = *reinterpret_cast<const float4*>(pB);
        As[0][ak + 0][arow] = a0.x; As[0][ak + 1][arow] = a0.y;
        As[0][ak + 2][arow] = a0.z; As[0][ak + 3][arow] = a0.w;
        As[0][ak + 0][arow + 64] = a1.x; As[0][ak + 1][arow + 64] = a1.y;
        As[0][ak + 2][arow + 64] = a1.z; As[0][ak + 3][arow + 64] = a1.w;
        Bs[0][ak + 0][arow] = bv.x; Bs[0][ak + 1][arow] = bv.y;
        Bs[0][ak + 2][arow] = bv.z; Bs[0][ak + 3][arow] = bv.w;
    }
    __syncthreads();

    for (int kt = 0; kt < 16; kt++) {
        const int cur = kt & 1;
        float4 a0, a1, bv;
        const bool more = (kt < 15);
        if (more) {
            const int k0 = (kt + 1) * 16;
            a0 = *reinterpret_cast<const float4*>(pA0 + k0);
            a1 = *reinterpret_cast<const float4*>(pA1 + k0);
            bv = *reinterpret_cast<const float4*>(pB + k0);
        }

#pragma unroll
        for (int kk = 0; kk < 16; kk++) {
            const u64* ap = reinterpret_cast<const u64*>(&As[cur][kk][ty * 8]);
            u64 pa0 = ap[0], pa1 = ap[1], pa2 = ap[2], pa3 = ap[3];
            float4 bv4 = *reinterpret_cast<const float4*>(&Bs[cur][kk][tx * 4]);
            u64 pb0 = packdup(bv4.x), pb1 = packdup(bv4.y);
            u64 pb2 = packdup(bv4.z), pb3 = packdup(bv4.w);
            acc2[0][0] = ffma2(pa0, pb0, acc2[0][0]);
            acc2[0][1] = ffma2(pa0, pb1, acc2[0][1]);
            acc2[0][2] = ffma2(pa0, pb2, acc2[0][2]);
            acc2[0][3] = ffma2(pa0, pb3, acc2[0][3]);
            acc2[1][0] = ffma2(pa1, pb0, acc2[1][0]);
            acc2[1][1] = ffma2(pa1, pb1, acc2[1][1]);
            acc2[1][2] = ffma2(pa1, pb2, acc2[1][2]);
            acc2[1][3] = ffma2(pa1, pb3, acc2[1][3]);
            acc2[2][0] = ffma2(pa2, pb0, acc2[2][0]);
            acc2[2][1] = ffma2(pa2, pb1, acc2[2][1]);
            acc2[2][2] = ffma2(pa2, pb2, acc2[2][2]);
            acc2[2][3] = ffma2(pa2, pb3, acc2[2][3]);
            acc2[3][0] = ffma2(pa3, pb0, acc2[3][0]);
            acc2[3][1] = ffma2(pa3, pb1, acc2[3][1]);
            acc2[3][2] = ffma2(pa3, pb2, acc2[3][2]);
            acc2[3][3] = ffma2(pa3, pb3, acc2[3][3]);
        }

        if (more) {
            const int nxt = cur ^ 1;
            As[nxt][ak + 0][arow] = a0.x; As[nxt][ak + 1][arow] = a0.y;
            As[nxt][ak + 2][arow] = a0.z; As[nxt][ak + 3][arow] = a0.w;
            As[nxt][ak + 0][arow + 64] = a1.x; As[nxt][ak + 1][arow + 64] = a1.y;
            As[nxt][ak + 2][arow + 64] = a1.z; As[nxt][ak + 3][arow + 64] = a1.w;
            Bs[nxt][ak + 0][arow] = bv.x; Bs[nxt][ak + 1][arow] = bv.y;
            Bs[nxt][ak + 2][arow] = bv.z; Bs[nxt][ak + 3][arow] = bv.w;
            __syncthreads();
        }
    }

    float4 b4 = *reinterpret_cast<const float4*>(bias + g0 + tx * 4);
#pragma unroll
    for (int i = 0; i < 4; i++) {
        float2 c0 = unpack2(acc2[i][0]), c1 = unpack2(acc2[i][1]);
        float2 c2 = unpack2(acc2[i][2]), c3 = unpack2(acc2[i][3]);
        size_t row0 = (size_t)(r0 + ty * 8 + 2 * i);
        float4 v0, v1;
        v0.x = c0.x + b4.x; v0.y = c1.x + b4.y; v0.z = c2.x + b4.z; v0.w = c3.x + b4.w;
        v1.x = c0.y + b4.x; v1.y = c1.y + b4.y; v1.z = c2.y + b4.z; v1.w = c3.y + b4.w;
        *reinterpret_cast<float4*>(&g_xg[row0 * G3 + g0 + tx * 4]) = v0;
        *reinterpret_cast<float4*>(&g_xg[(row0 + 1) * G3 + g0 + tx * 4]) = v1;
    }
}

// ---------------------------------------------------------------------------
// Persistent GRU scan — ROUND-6 VERBATIM (best measured; frozen).
// ---------------------------------------------------------------------------
__global__ void __cluster_dims__(4, 1, 1) __launch_bounds__(512, 1)
gru_scan_kernel(const float* __restrict__ Whh,   // [768,256]
                const float* __restrict__ bhh,   // [768]
                float* __restrict__ out, int ostride,
                float* __restrict__ out2, int ostride2)  // may be null
{
    __shared__ alignas(16) float rbuf[2][4][2][64];  // [parity][rank][sb][unit]
    __shared__ alignas(8)  u64   mbars[2];

    const int c    = blockIdx.x;               // cluster rank
    const int tid  = threadIdx.x;
    const int warp = tid >> 5;
    const int lane = tid & 31;
    const int ul   = warp * 4 + (lane >> 3);   // local unit 0..63
    const int jg   = c * 64 + ul;              // global hidden unit
    const int kc   = lane & 7;                 // k-slice id
    const bool leader = kc == 0;
    const int b0   = blockIdx.y * 2;

    // weights, interleaved-k order: thread kc owns k = 32*i + 4*kc .. +3
    u64 wr2[16], wz2[16], wn2[16];
#pragma unroll
    for (int i = 0; i < 8; i++) {
        const int k4 = 32 * i + 4 * kc;
        wr2[2*i]   = *reinterpret_cast<const u64*>(Whh + (size_t)jg * HH + k4);
        wr2[2*i+1] = *reinterpret_cast<const u64*>(Whh + (size_t)jg * HH + k4 + 2);
        wz2[2*i]   = *reinterpret_cast<const u64*>(Whh + (size_t)(256 + jg) * HH + k4);
        wz2[2*i+1] = *reinterpret_cast<const u64*>(Whh + (size_t)(256 + jg) * HH + k4 + 2);
        wn2[2*i]   = *reinterpret_cast<const u64*>(Whh + (size_t)(512 + jg) * HH + k4);
        wn2[2*i+1] = *reinterpret_cast<const u64*>(Whh + (size_t)(512 + jg) * HH + k4 + 2);
    }
    float bhr = 0.f, bhz = 0.f, bhn = 0.f;
    if (leader) { bhr = bhh[jg]; bhz = bhh[256 + jg]; bhn = bhh[512 + jg]; }

    // zero parity-0 buffer (512 floats)
    ((float*)rbuf)[tid] = 0.f;
    const uint32_t mb = smem_u32(mbars);
    const uint32_t hb = smem_u32(rbuf);
    if (tid == 0) {
        asm volatile("mbarrier.init.shared.b64 [%0], 1;" :: "r"(mb)     : "memory");
        asm volatile("mbarrier.init.shared.b64 [%0], 1;" :: "r"(mb + 8) : "memory");
    }
    __syncthreads();
    asm volatile("barrier.cluster.arrive.aligned;" ::: "memory");
    asm volatile("barrier.cluster.wait.aligned;"   ::: "memory");

    // hoisted per-rank remote bases
    uint32_t hb_r[4], mb_r[4];
#pragma unroll
    for (int r = 0; r < 4; r++) {
        asm volatile("mapa.shared::cluster.u32 %0, %1, %2;" : "=r"(hb_r[r]) : "r"(hb), "r"(r));
        asm volatile("mapa.shared::cluster.u32 %0, %1, %2;" : "=r"(mb_r[r]) : "r"(mb), "r"(r));
    }

    // prefetch xg for t=0 (leaders)
    float xpr[2], xpz[2], xpn[2];
    if (leader) {
#pragma unroll
        for (int sb = 0; sb < 2; sb++) {
            size_t base = ((size_t)(b0 + sb) * SS) * G3;
            xpr[sb] = __ldg(&g_xg[base + jg]);
            xpz[sb] = __ldg(&g_xg[base + 256 + jg]);
            xpn[sb] = __ldg(&g_xg[base + 512 + jg]);
        }
    }

    const int hrank = jg >> 6, hidx = jg & 63;
    int ph0 = 0, ph1 = 0;

    for (int t = 0; t < SS; t++) {
        const int p = t & 1, pq = p ^ 1;
        if (tid == 0) {
            asm volatile("mbarrier.arrive.expect_tx.shared.b64 _, [%0], %1;"
                         :: "r"(mb + pq * 8), "r"(1536u) : "memory");
        }
        float xr[2], xz[2], xn[2];
        if (leader) {
#pragma unroll
            for (int sb = 0; sb < 2; sb++) { xr[sb]=xpr[sb]; xz[sb]=xpz[sb]; xn[sb]=xpn[sb]; }
            const int tn = (t + 1 < SS) ? t + 1 : t;
#pragma unroll
            for (int sb = 0; sb < 2; sb++) {
                size_t base = ((size_t)(b0 + sb) * SS + tn) * G3;
                xpr[sb] = __ldg(&g_xg[base + jg]);
                xpz[sb] = __ldg(&g_xg[base + 256 + jg]);
                xpn[sb] = __ldg(&g_xg[base + 512 + jg]);
            }
        }

#pragma unroll
        for (int sb = 0; sb < 2; sb++) {
            u64 aR = 0ull, aZ = 0ull, aN = 0ull;
#pragma unroll
            for (int i = 0; i < 8; i++) {
                const int k4 = 32 * i + 4 * kc;
                ulonglong2 hv = *reinterpret_cast<const ulonglong2*>(
                    &rbuf[p][k4 >> 6][sb][k4 & 63]);
                aR = ffma2(wr2[2*i],   hv.x, aR);
                aZ = ffma2(wz2[2*i],   hv.x, aZ);
                aN = ffma2(wn2[2*i],   hv.x, aN);
                aR = ffma2(wr2[2*i+1], hv.y, aR);
                aZ = ffma2(wz2[2*i+1], hv.y, aZ);
                aN = ffma2(wn2[2*i+1], hv.y, aN);
            }
            float2 fR = unpack2(aR), fZ = unpack2(aZ), fN = unpack2(aN);
            float sR = fR.x + fR.y, sZ = fZ.x + fZ.y, sN = fN.x + fN.y;
#pragma unroll
            for (int d = 4; d; d >>= 1) {
                sR += __shfl_down_sync(0xffffffffu, sR, d);
                sZ += __shfl_down_sync(0xffffffffu, sZ, d);
                sN += __shfl_down_sync(0xffffffffu, sN, d);
            }
            if (leader) {
                float er = __expf(-(xr[sb] + sR + bhr));
                float r  = rcpa(1.f + er);
                float ez = __expf(-(xz[sb] + sZ + bhz));
                float z  = rcpa(1.f + ez);
                float na = xn[sb] + r * (sN + bhn);
                float en = __expf(-2.f * na);
                float n  = (1.f - en) * rcpa(1.f + en);
                float hold = rbuf[p][hrank][sb][hidx];
                float hnew = n + z * (hold - n);

                size_t row = (size_t)(b0 + sb) * SS + t;
                out[row * ostride + jg] = hnew;
                if (out2) out2[row * ostride2 + jg] = hnew;

                rbuf[pq][c][sb][ul] = hnew;   // local write of own slice
            }
        }
        __syncthreads();

        // ship own 512B slice to the 3 other ranks as bulk DMA
        if (tid == 0) {
            asm volatile("fence.proxy.async.shared::cta;" ::: "memory");
            const uint32_t off = (uint32_t)(pq * 2048 + c * 512);
            const uint32_t src = hb + off;
#pragma unroll
            for (int r = 0; r < 4; r++) {
                if (r != c) {
                    asm volatile(
                        "cp.async.bulk.shared::cluster.shared::cta.mbarrier::complete_tx::bytes "
                        "[%0], [%1], %2, [%3];"
                        :: "r"(hb_r[r] + off), "r"(src), "r"(512u),
                           "r"(mb_r[r] + (uint32_t)(pq * 8)) : "memory");
                }
            }
        }

        // wait for the 3 remote slices of step t+1
        {
            uint32_t maddr = mb + pq * 8;
            uint32_t parity = pq ? ph1 : ph0;
            uint32_t done;
            asm volatile(
                "{\n\t.reg .pred p;\n\t"
                "mbarrier.try_wait.parity.acquire.cta.shared::cta.b64 p, [%1], %2;\n\t"
                "selp.b32 %0, 1, 0, p;\n\t}"
                : "=r"(done) : "r"(maddr), "r"(parity) : "memory");
            if (!done) {
                asm volatile(
                    "{\n\t.reg .pred P1;\n\t"
                    "WL_%=:\n\t"
                    "mbarrier.try_wait.parity.acquire.cta.shared::cta.b64 P1, [%0], %1, 0x989680;\n\t"
                    "@P1 bra.uni WD_%=;\n\t"
                    "bra.uni WL_%=;\n\t"
                    "WD_%=:\n\t}"
                    :: "r"(maddr), "r"(parity) : "memory");
            }
            if (pq) ph1 ^= 1; else ph0 ^= 1;
        }
    }
}

// ---------------------------------------------------------------------------
extern "C" void kernel_launch(void* const* d_in, const int* in_sizes, int n_in,
                              void* d_out, int out_size)
{
    (void)in_sizes; (void)n_in; (void)out_size;
    const float* inputs = (const float*)d_in[0];
    const float* W_ih0  = (const float*)d_in[1];
    const float* W_hh0  = (const float*)d_in[2];
    const float* b_ih0  = (const float*)d_in[3];
    const float* b_hh0  = (const float*)d_in[4];
    const float* W_ih1  = (const float*)d_in[5];
    const float* W_hh1  = (const float*)d_in[6];
    const float* b_ih1  = (const float*)d_in[7];
    const float* b_hh1  = (const float*)d_in[8];

    float* out    = (float*)d_out;
    float* h2     = out;                               // [B,S,H]
    float* concat = out + (size_t)BB * SS * HH;        // [B,S,2H]

    dim3 gemm_grid(G3 / 64, (BB * SS) / 128);
    dim3 scan_grid(4, BB / 2);

    // Layer 0
    gemm_xg_kernel<<<gemm_grid, 256>>>(inputs, (long)II, W_ih0, b_ih0);
    gru_scan_kernel<<<scan_grid, 512>>>(W_hh0, b_hh0, concat, 2 * HH, nullptr, 0);

    // Layer 1 (reads h1 from concat, lda = 512)
    gemm_xg_kernel<<<gemm_grid, 256>>>(concat, (long)(2 * HH), W_ih1, b_ih1);
    gru_scan_kernel<<<scan_grid, 512>>>(W_hh1, b_hh1, concat + HH, 2 * HH, h2, HH);
}